// round 1
// baseline (speedup 1.0000x reference)
#include <cuda_runtime.h>
#include <cuda_bf16.h>

// Problem constants
#define BATCH 16
#define CIN   32
#define COUT  64
#define H_IN  224
#define W_IN  224
#define H_OUT 222
#define W_OUT 222

// Tiling
#define TH 16          // output rows per block
#define TW 32          // output cols per block
#define OB 16          // output channels per block
#define IN_H (TH + 2)  // 18
#define IN_WS 36       // padded smem row stride (34 needed, pad to 36 for 16B alignment)
#define CH_STRIDE (IN_H * IN_WS)       // 648 floats per channel
#define SMEM_IN_FLOATS (CIN * CH_STRIDE)   // 20736
#define SMEM_W_FLOATS  (CIN * OB * 9)      // 4608
#define SMEM_TOTAL_BYTES ((SMEM_IN_FLOATS + SMEM_W_FLOATS) * 4)  // 101376

__global__ void __launch_bounds__(256)
quanv_conv_kernel(const float* __restrict__ x,
                  const float* __restrict__ w,
                  float* __restrict__ out)
{
    extern __shared__ float smem[];
    float* s_in = smem;                    // [CIN][IN_H][IN_WS]
    float* s_w  = smem + SMEM_IN_FLOATS;   // [CIN][OB][9]

    const int tid = threadIdx.x;
    const int z   = blockIdx.z;
    const int b   = z >> 2;        // batch
    const int ob  = z & 3;         // output-channel block (4 blocks of 16)
    const int x0  = blockIdx.x * TW;
    const int y0  = blockIdx.y * TH;

    // ---- Stage input tile: 32 channels x 18 x 36 (34 valid cols) ----
    {
        const float* xb = x + (size_t)b * CIN * H_IN * W_IN;
        #pragma unroll 1
        for (int idx = tid; idx < SMEM_IN_FLOATS; idx += 256) {
            int c   = idx / CH_STRIDE;
            int rem = idx - c * CH_STRIDE;
            int r   = rem / IN_WS;
            int col = rem - r * IN_WS;
            int gy  = y0 + r;
            int gx  = x0 + col;
            float v = 0.0f;
            if (col < 34 && gy < H_IN && gx < W_IN)
                v = xb[(c * H_IN + gy) * W_IN + gx];
            s_in[idx] = v;
        }
    }

    // ---- Stage weight slice: [c][o_local][tap], o = ob*16 + o_local ----
    {
        #pragma unroll 1
        for (int idx = tid; idx < SMEM_W_FLOATS; idx += 256) {
            int c   = idx / (OB * 9);
            int rem = idx - c * (OB * 9);
            int ol  = rem / 9;
            int t   = rem - ol * 9;
            s_w[idx] = w[((ob * OB + ol) * CIN + c) * 9 + t];
        }
    }

    __syncthreads();

    // ---- Compute: each thread = 1 row x 8 cols x 4 output channels ----
    const int og  = tid >> 6;           // 0..3  -> 4 o's each
    const int pid = tid & 63;
    const int pr  = pid >> 2;           // 0..15 local output row
    const int pc  = (pid & 3) << 3;     // 0,8,16,24 local output col base

    float acc[4][8];
    #pragma unroll
    for (int oo = 0; oo < 4; ++oo)
        #pragma unroll
        for (int p = 0; p < 8; ++p) acc[oo][p] = 0.0f;

    #pragma unroll 1
    for (int c = 0; c < CIN; ++c) {
        // weights for this channel, 4 outputs x 9 taps (broadcast LDS)
        float wreg[4][9];
        const float* wp = s_w + c * (OB * 9) + (og * 4) * 9;
        #pragma unroll
        for (int oo = 0; oo < 4; ++oo)
            #pragma unroll
            for (int t = 0; t < 9; ++t) wreg[oo][t] = wp[oo * 9 + t];

        // input rows pr..pr+2, cols pc..pc+9 (vectorized, 16B aligned)
        float in[3][10];
        const float* sc = s_in + c * CH_STRIDE;
        #pragma unroll
        for (int dy = 0; dy < 3; ++dy) {
            const float* rowp = sc + (pr + dy) * IN_WS + pc;
            float4 a = *(const float4*)(rowp);
            float4 bq = *(const float4*)(rowp + 4);
            float2 cq = *(const float2*)(rowp + 8);
            in[dy][0] = a.x; in[dy][1] = a.y; in[dy][2] = a.z; in[dy][3] = a.w;
            in[dy][4] = bq.x; in[dy][5] = bq.y; in[dy][6] = bq.z; in[dy][7] = bq.w;
            in[dy][8] = cq.x; in[dy][9] = cq.y;
        }

        #pragma unroll
        for (int oo = 0; oo < 4; ++oo)
            #pragma unroll
            for (int dy = 0; dy < 3; ++dy)
                #pragma unroll
                for (int dx = 0; dx < 3; ++dx) {
                    float wv = wreg[oo][dy * 3 + dx];
                    #pragma unroll
                    for (int p = 0; p < 8; ++p)
                        acc[oo][p] = fmaf(in[dy][p + dx], wv, acc[oo][p]);
                }
    }

    // ---- Store: out[((o*BATCH + b)*H_OUT + y)*W_OUT + x] ----
    const int y = y0 + pr;
    if (y < H_OUT) {
        #pragma unroll
        for (int oo = 0; oo < 4; ++oo) {
            int o = ob * OB + og * 4 + oo;
            float* op = out + ((size_t)(o * BATCH + b) * H_OUT + y) * W_OUT;
            #pragma unroll
            for (int p = 0; p < 8; ++p) {
                int xx = x0 + pc + p;
                if (xx < W_OUT) op[xx] = acc[oo][p];
            }
        }
    }
}

extern "C" void kernel_launch(void* const* d_in, const int* in_sizes, int n_in,
                              void* d_out, int out_size)
{
    const float* x = (const float*)d_in[0];
    const float* w = (const float*)d_in[1];
    float* out = (float*)d_out;

    static bool attr_set = false;
    if (!attr_set) {
        cudaFuncSetAttribute(quanv_conv_kernel,
                             cudaFuncAttributeMaxDynamicSharedMemorySize,
                             SMEM_TOTAL_BYTES);
        attr_set = true;
    }

    dim3 grid((W_OUT + TW - 1) / TW,   // 7
              (H_OUT + TH - 1) / TH,   // 14
              BATCH * 4);              // 64 (batch * o-blocks)
    quanv_conv_kernel<<<grid, 256, SMEM_TOTAL_BYTES>>>(x, w, out);
}

// round 3
// speedup vs baseline: 3.5861x; 3.5861x over previous
#include <cuda_runtime.h>
#include <cuda_bf16.h>
#include <cstdint>

// ---------------- Problem constants ----------------
#define BATCH   16
#define CIN     32
#define COUT    64
#define WH_IN   224
#define WH_OUT  222
#define KDIM    288                 // 32 ch * 9 taps
#define KSTEPS  18                  // 288 / 16
#define NTILES  (BATCH * WH_OUT * 2)  // 7104 = 148 * 48
#define TILES_PER_CTA 48

#define OPLANE  (BATCH * WH_OUT * WH_OUT)   // 788544 floats per out-channel

// ---------------- SMEM layout (bytes) ----------------
#define WSTRIDE   296                         // bf16 elems per n-row (288 + pad, bank-clean)
#define SM_WHI    0
#define SM_WLO    (COUT * WSTRIDE * 2)        // 37888
#define SM_LUT    (2 * COUT * WSTRIDE * 2)    // 75776
#define IN_STRIDE 132                         // fp32 per staged row
#define IN_BYTES  (96 * IN_STRIDE * 4)        // 50688
#define SM_IN0    (SM_LUT + 1152)             // 76928 (16B aligned)
#define SM_IN1    (SM_IN0 + IN_BYTES)         // 127616
#define SMEM_BYTES (SM_IN1 + IN_BYTES)        // 178304

// ---------------- low-level helpers ----------------
static __device__ __forceinline__ uint32_t smem_u32(const void* p) {
    uint32_t a;
    asm("{ .reg .u64 t; cvta.to.shared.u64 t, %1; cvt.u32.u64 %0, t; }" : "=r"(a) : "l"(p));
    return a;
}
static __device__ __forceinline__ float lds_f32(uint32_t a) {
    float v; asm volatile("ld.shared.f32 %0, [%1];" : "=f"(v) : "r"(a)); return v;
}
static __device__ __forceinline__ uint32_t lds_u32(uint32_t a) {
    uint32_t v; asm volatile("ld.shared.b32 %0, [%1];" : "=r"(v) : "r"(a)); return v;
}
static __device__ __forceinline__ int lds_s32(uint32_t a) {
    int v; asm volatile("ld.shared.b32 %0, [%1];" : "=r"(v) : "r"(a)); return v;
}
static __device__ __forceinline__ void sts_u16(uint32_t a, uint32_t v) {
    asm volatile("st.shared.u16 [%0], %1;" :: "r"(a), "r"(v));
}
static __device__ __forceinline__ void sts_s32(uint32_t a, int v) {
    asm volatile("st.shared.b32 [%0], %1;" :: "r"(a), "r"(v));
}
// pack two f32 -> bf16x2 word: LOW half = v0, HIGH half = v1
static __device__ __forceinline__ uint32_t pack_bf16x2(float v0, float v1) {
    uint32_t w;
    asm("cvt.rn.bf16x2.f32 %0, %1, %2;" : "=r"(w) : "f"(v1), "f"(v0));
    return w;
}
static __device__ __forceinline__ void cp_async16(uint32_t dst, const void* src) {
    asm volatile("cp.async.cg.shared.global [%0], [%1], 16;" :: "r"(dst), "l"(src));
}
#define CP_COMMIT() asm volatile("cp.async.commit_group;" ::: "memory")
#define CP_WAIT0()  asm volatile("cp.async.wait_group 0;" ::: "memory")

// mma.sync m16n8k16 row.col bf16 -> f32, accumulate in place
static __device__ __forceinline__ void mma_bf16(float* d, const uint32_t* a,
                                                uint32_t b0, uint32_t b1) {
    asm volatile(
        "mma.sync.aligned.m16n8k16.row.col.f32.bf16.bf16.f32 "
        "{%0,%1,%2,%3}, {%4,%5,%6,%7}, {%8,%9}, {%0,%1,%2,%3};"
        : "+f"(d[0]), "+f"(d[1]), "+f"(d[2]), "+f"(d[3])
        : "r"(a[0]), "r"(a[1]), "r"(a[2]), "r"(a[3]), "r"(b0), "r"(b1));
}

// stage one tile's input patch (96 rows x 132 fp32) via cp.async
static __device__ __forceinline__ void stage_tile(const float* __restrict__ x,
                                                  int t, uint32_t buf, int tid) {
    const int b    = t / (WH_OUT * 2);
    const int rr   = t - b * (WH_OUT * 2);
    const int y    = rr >> 1;
    const int xs   = (rr & 1) ? 92 : 0;
    #pragma unroll 1
    for (int i = tid; i < 96 * 33; i += 256) {
        const int row = i / 33;              // row = c*3 + dy
        const int qq  = i - row * 33;
        const int c   = row / 3;
        const int dy  = row - c * 3;
        const float* g = x + ((size_t)(b * CIN + c) * WH_IN + (y + dy)) * WH_IN + xs + qq * 4;
        cp_async16(buf + (uint32_t)(row * IN_STRIDE + qq * 4) * 4, g);
    }
    CP_COMMIT();
}

__global__ void __launch_bounds__(256, 1)
quanv_mma_kernel(const float* __restrict__ x, const float* __restrict__ w,
                 float* __restrict__ out)
{
    extern __shared__ char smem[];
    const uint32_t sbase = smem_u32(smem);
    const uint32_t whi_a = sbase + SM_WHI;
    const uint32_t wlo_a = sbase + SM_WLO;
    const uint32_t lut_a = sbase + SM_LUT;

    const int tid = threadIdx.x;
    const int wid = tid >> 5;
    const int lid = tid & 31;
    const int r   = lid >> 2;     // group id 0..7
    const int q   = lid & 3;

    // ---- one-time: split weights into [n][k] bf16 hi/lo (K-stride 296) ----
    #pragma unroll 1
    for (int e = tid; e < COUT * KDIM; e += 256) {
        const int o = e / KDIM;
        const int k = e - o * KDIM;
        const float wv = w[e];                       // w is [o][k] contiguous
        const uint32_t hw = pack_bf16x2(wv, 0.0f);
        const float hf = __uint_as_float(hw << 16);
        const uint32_t lw = pack_bf16x2(wv - hf, 0.0f);
        const uint32_t off = (uint32_t)(o * WSTRIDE + k) * 2;
        sts_u16(whi_a + off, hw & 0xFFFFu);
        sts_u16(wlo_a + off, lw & 0xFFFFu);
    }
    // ---- one-time: im2col byte-offset LUT ----
    for (int k = tid; k < KDIM; k += 256) {
        const int c = k / 9, t9 = k - c * 9;
        sts_s32(lut_a + k * 4, ((c * 3 + t9 / 3) * IN_STRIDE + (t9 % 3)) * 4);
    }
    __syncthreads();

    // ---- persistent tile loop with cp.async double buffering ----
    const int t0 = blockIdx.x * TILES_PER_CTA;
    stage_tile(x, t0, sbase + SM_IN0, tid);

    #pragma unroll 1
    for (int it = 0; it < TILES_PER_CTA; ++it) {
        const int t = t0 + it;
        CP_WAIT0();
        __syncthreads();                       // buf[it&1] staged & prev compute done
        if (it + 1 < TILES_PER_CTA)
            stage_tile(x, t + 1, sbase + ((it + 1) & 1 ? SM_IN1 : SM_IN0), tid);

        const uint32_t inb = sbase + ((it & 1) ? SM_IN1 : SM_IN0);
        const int b    = t / (WH_OUT * 2);
        const int rr   = t - b * (WH_OUT * 2);
        const int y    = rr >> 1;
        const int half = rr & 1;
        const int x0   = half ? 94 : 0;
        const int xoff = half ? 2  : 0;

        float acc[8][4];
        #pragma unroll
        for (int nb = 0; nb < 8; ++nb)
            #pragma unroll
            for (int j = 0; j < 4; ++j) acc[nb][j] = 0.0f;

        // pixel base address for this lane (row r of the warp's 16-px block)
        const uint32_t pix = inb + (uint32_t)(xoff + wid * 16 + r) * 4;
        const uint32_t lutq = lut_a + (uint32_t)(q * 2) * 4;

        #pragma unroll 3
        for (int ks = 0; ks < KSTEPS; ++ks) {
            const int kb = ks * 16 + q * 2;
            const uint32_t lp = lutq + (uint32_t)(ks * 16) * 4;
            const int o0 = lds_s32(lp);
            const int o1 = lds_s32(lp + 4);
            const int o8 = lds_s32(lp + 32);
            const int o9 = lds_s32(lp + 36);

            // 8 fp32 elements: rows r and r+8, k = kb,kb+1,kb+8,kb+9
            const float v00 = lds_f32(pix + o0);
            const float v01 = lds_f32(pix + o1);
            const float v02 = lds_f32(pix + o8);
            const float v03 = lds_f32(pix + o9);
            const float v10 = lds_f32(pix + 32 + o0);
            const float v11 = lds_f32(pix + 32 + o1);
            const float v12 = lds_f32(pix + 32 + o8);
            const float v13 = lds_f32(pix + 32 + o9);

            uint32_t ahi[4], alo[4];
            {
                const uint32_t h0 = pack_bf16x2(v00, v01);
                alo[0] = pack_bf16x2(v00 - __uint_as_float(h0 << 16),
                                     v01 - __uint_as_float(h0 & 0xFFFF0000u));
                ahi[0] = h0;
                const uint32_t h1 = pack_bf16x2(v10, v11);
                alo[1] = pack_bf16x2(v10 - __uint_as_float(h1 << 16),
                                     v11 - __uint_as_float(h1 & 0xFFFF0000u));
                ahi[1] = h1;
                const uint32_t h2 = pack_bf16x2(v02, v03);
                alo[2] = pack_bf16x2(v02 - __uint_as_float(h2 << 16),
                                     v03 - __uint_as_float(h2 & 0xFFFF0000u));
                ahi[2] = h2;
                const uint32_t h3 = pack_bf16x2(v12, v13);
                alo[3] = pack_bf16x2(v12 - __uint_as_float(h3 << 16),
                                     v13 - __uint_as_float(h3 & 0xFFFF0000u));
                ahi[3] = h3;
            }

            // B fragment base: n = nb*8 + r, k = kb  (bank-conflict-free, stride 296)
            const uint32_t bb = (uint32_t)(r * WSTRIDE + kb) * 2;
            #pragma unroll
            for (int nb = 0; nb < 8; ++nb) {
                const uint32_t boff = bb + (uint32_t)(nb * 8 * WSTRIDE) * 2;
                const uint32_t bh0 = lds_u32(whi_a + boff);
                const uint32_t bh1 = lds_u32(whi_a + boff + 16);
                const uint32_t bl0 = lds_u32(wlo_a + boff);
                const uint32_t bl1 = lds_u32(wlo_a + boff + 16);
                mma_bf16(acc[nb], ahi, bh0, bh1);
                mma_bf16(acc[nb], ahi, bl0, bl1);
                mma_bf16(acc[nb], alo, bh0, bh1);
            }
        }

        // ---- store: out[((o*16 + b)*222 + y)*222 + x0 + m] ----
        {
            float* ob = out + (size_t)(b * WH_OUT + y) * WH_OUT + x0 + wid * 16 + r
                            + (size_t)(2 * q) * OPLANE;
            #pragma unroll
            for (int nb = 0; nb < 8; ++nb) {
                float* p = ob + (size_t)(nb * 8) * OPLANE;
                p[0]          = acc[nb][0];   // (m, o)
                p[OPLANE]     = acc[nb][1];   // (m, o+1)
                p[8]          = acc[nb][2];   // (m+8, o)
                p[OPLANE + 8] = acc[nb][3];   // (m+8, o+1)
            }
        }
    }
}

extern "C" void kernel_launch(void* const* d_in, const int* in_sizes, int n_in,
                              void* d_out, int out_size)
{
    const float* x = (const float*)d_in[0];
    const float* w = (const float*)d_in[1];
    float* out = (float*)d_out;

    static bool attr_set = false;
    if (!attr_set) {
        cudaFuncSetAttribute(quanv_mma_kernel,
                             cudaFuncAttributeMaxDynamicSharedMemorySize, SMEM_BYTES);
        attr_set = true;
    }
    quanv_mma_kernel<<<148, 256, SMEM_BYTES>>>(x, w, out);
}